// round 14
// baseline (speedup 1.0000x reference)
#include <cuda_runtime.h>
#include <math.h>

// Problem constants
#define Nn 128
#define Cc 64
#define Tt 128
#define Vv 25
#define Rr 8
#define Hh 12

// Scratch (device globals; no allocation allowed)
__device__ float g_xm[Nn * Cc * Vv];                 // mean over T     (0.8 MB)
__device__ float g_relT[Nn * Vv * Vv * Rr];          // tanh relation, TRANSPOSED [n][e][r]
__device__ float g_a[Nn * Vv];                       // SE joint gate   (12.8 KB)

// ---------- f32x2 helpers (explicit PTX packed fp32; ptxas never auto-fuses) ----------
__device__ __forceinline__ unsigned long long pack2(float lo, float hi) {
    unsigned long long r;
    asm("mov.b64 %0, {%1, %2};" : "=l"(r) : "f"(lo), "f"(hi));
    return r;
}
__device__ __forceinline__ void unpack2(unsigned long long x, float& lo, float& hi) {
    asm("mov.b64 {%0, %1}, %2;" : "=f"(lo), "=f"(hi) : "l"(x));
}
__device__ __forceinline__ unsigned long long fma2(unsigned long long a,
                                                   unsigned long long b,
                                                   unsigned long long c) {
    unsigned long long d;
    asm("fma.rn.f32x2 %0, %1, %2, %3;" : "=l"(d) : "l"(a), "l"(b), "l"(c));
    return d;
}
__device__ __forceinline__ unsigned long long add2(unsigned long long a,
                                                   unsigned long long b) {
    unsigned long long d;
    asm("add.rn.f32x2 %0, %1, %2;" : "=l"(d) : "l"(a), "l"(b));
    return d;
}

// ================= Kernel 1: xm[n,c,v] = mean_t x[n,c,t,v] =================
// Proven ~19.4us @ ~71% DRAM.
__global__ void __launch_bounds__(200) k1_meanT(const float* __restrict__ x) {
    const int b = blockIdx.x;                 // n*C + c
    const int j = threadIdx.x;                // 0..199
    const float4* xp4 = reinterpret_cast<const float4*>(x + (size_t)b * (Tt * Vv));

    float4 a0 = xp4[j];
    float4 a1 = xp4[j + 200];
    float4 a2 = xp4[j + 400];
    float4 a3 = xp4[j + 600];

    __shared__ float red[800];
    red[4 * j + 0] = a0.x + a1.x + a2.x + a3.x;
    red[4 * j + 1] = a0.y + a1.y + a2.y + a3.y;
    red[4 * j + 2] = a0.z + a1.z + a2.z + a3.z;
    red[4 * j + 3] = a0.w + a1.w + a2.w + a3.w;
    __syncthreads();

    if (j < Vv) {
        float tot = 0.f;
        #pragma unroll
        for (int p = 0; p < 32; p++) tot += red[j + Vv * p];
        g_xm[b * Vv + j] = tot * (1.0f / Tt);
    }
}

// ============ Kernel 2: SE gate + transposed relation tensor ============
// One block per n, 512 threads. Writes g_a[n,v] and g_relT[n][e=u*25+v][r].
__global__ void __launch_bounds__(512) k2_rel(
        const float* __restrict__ w1, const float* __restrict__ b1,
        const float* __restrict__ w2, const float* __restrict__ b2,
        const float* __restrict__ sw1, const float* __restrict__ sb1,
        const float* __restrict__ sw2, const float* __restrict__ sb2) {
    const int n = blockIdx.x;
    const int tid = threadIdx.x;
    const int NT = 512;

    __shared__ float xm_sh[Cc * Vv];
    __shared__ float w1s[Rr * Cc], w2s[Rr * Cc];
    __shared__ float sw1s[Hh * Vv], sw2s[Vv * Hh];
    __shared__ float b1s[Rr], b2s[Rr], sb1s[Hh], sb2s[Vv];
    __shared__ float s_sh[Vv], h_sh[Hh];
    __shared__ float x1_sh[Rr * Vv], x2_sh[Rr * Vv];

    {
        const float4* xm4 = reinterpret_cast<const float4*>(g_xm + n * Cc * Vv);
        float4* sh4 = reinterpret_cast<float4*>(xm_sh);
        if (tid < 400) sh4[tid] = xm4[tid];
    }
    for (int i = tid; i < Rr * Cc; i += NT) { w1s[i] = w1[i]; w2s[i] = w2[i]; }
    for (int i = tid; i < Hh * Vv; i += NT) { sw1s[i] = sw1[i]; sw2s[i] = sw2[i]; }
    if (tid < Rr) { b1s[tid] = b1[tid]; b2s[tid] = b2[tid]; }
    if (tid < Hh) sb1s[tid] = sb1[tid];
    if (tid < Vv) sb2s[tid] = sb2[tid];
    __syncthreads();

    if (tid < Vv) {
        float acc = 0.f;
        for (int c = 0; c < Cc; c++) acc += xm_sh[c * Vv + tid];
        s_sh[tid] = acc * (1.0f / Cc);
    }
    if (tid >= 64 && tid < 64 + Rr * Vv) {
        int i = tid - 64;
        int r = i / Vv, v = i % Vv;
        float acc1 = b1s[r], acc2 = b2s[r];
        for (int c = 0; c < Cc; c++) {
            float xm = xm_sh[c * Vv + v];
            acc1 += w1s[r * Cc + c] * xm;
            acc2 += w2s[r * Cc + c] * xm;
        }
        x1_sh[i] = acc1;
        x2_sh[i] = acc2;
    }
    __syncthreads();
    if (tid < Hh) {
        float acc = sb1s[tid];
        for (int v = 0; v < Vv; v++) acc += sw1s[tid * Vv + v] * s_sh[v];
        h_sh[tid] = fmaxf(acc, 0.f);
    }
    __syncthreads();
    if (tid < Vv) {
        float acc = sb2s[tid];
        for (int q = 0; q < Hh; q++) acc += sw2s[tid * Hh + q] * h_sh[q];
        g_a[n * Vv + tid] = 1.0f / (1.0f + expf(-acc));
    }

    float4* relp4 = reinterpret_cast<float4*>(g_relT + (size_t)n * (Vv * Vv * Rr));
    for (int e = tid; e < Vv * Vv; e += NT) {
        const int u = e / Vv, v = e % Vv;
        float4 lo, hi;
        lo.x = tanhf(x1_sh[0 * Vv + u] - x2_sh[0 * Vv + v]);
        lo.y = tanhf(x1_sh[1 * Vv + u] - x2_sh[1 * Vv + v]);
        lo.z = tanhf(x1_sh[2 * Vv + u] - x2_sh[2 * Vv + v]);
        lo.w = tanhf(x1_sh[3 * Vv + u] - x2_sh[3 * Vv + v]);
        hi.x = tanhf(x1_sh[4 * Vv + u] - x2_sh[4 * Vv + v]);
        hi.y = tanhf(x1_sh[5 * Vv + u] - x2_sh[5 * Vv + v]);
        hi.z = tanhf(x1_sh[6 * Vv + u] - x2_sh[6 * Vv + v]);
        hi.w = tanhf(x1_sh[7 * Vv + u] - x2_sh[7 * Vv + v]);
        relp4[2 * e]     = lo;
        relp4[2 * e + 1] = hi;
    }
}

// ============ Kernel 3 (R5 f32x2 body, measured 63.8us, + relT recon) ============
// One block per (n,c), 64 threads; each thread computes rows t and t+64 as a
// packed f32x2 pair. Weights duplicated into (w,w) pairs, rows padded to 26
// pairs (208B, 16B-aligned) -> 12 LDS.128 + 1 LDS.64 + 13 FFMA2 per u-row.
__global__ void __launch_bounds__(64) k3_gemm(const float* __restrict__ x,
                                              const float* __restrict__ Astat,
                                              const float* __restrict__ w4,
                                              const float* __restrict__ b4,
                                              float* __restrict__ out) {
    __shared__ float xs[Tt * Vv];                       // 12.8 KB; reused as out staging
    __shared__ __align__(16) float2 a2sh[Vv * 26];      // duplicated weight pairs

    const int b = blockIdx.x;           // n*C + c
    const int n = b >> 6;
    const int c = b & 63;
    const int tid = threadIdx.x;        // 0..63

    // Load x tile (float4, coalesced)
    const float4* xp4 = reinterpret_cast<const float4*>(x + (size_t)b * (Tt * Vv));
    float4* xs4 = reinterpret_cast<float4*>(xs);
    #pragma unroll
    for (int i = tid; i < (Tt * Vv) / 4; i += 64) xs4[i] = xp4[i];

    // Reconstruct weights from relT (coalesced float4 reads), duplicate into pairs:
    // w = (sum_r w4[c,r]*relT[e][r] + b4[c] + A[u,v]) * a[n,v]
    {
        const float4 wA = *reinterpret_cast<const float4*>(w4 + c * Rr);
        const float4 wB = *reinterpret_cast<const float4*>(w4 + c * Rr + 4);
        const float bias = __ldg(b4 + c);
        const float4* relp4 = reinterpret_cast<const float4*>(g_relT + (size_t)n * (Vv * Vv * Rr));
        const float* ap = g_a + n * Vv;
        #pragma unroll 1
        for (int e = tid; e < Vv * Vv; e += 64) {
            int u = e / Vv, v = e - u * Vv;
            float4 lo = relp4[2 * e];
            float4 hi = relp4[2 * e + 1];
            float acc = bias + __ldg(Astat + e);
            acc += wA.x * lo.x + wA.y * lo.y + wA.z * lo.z + wA.w * lo.w;
            acc += wB.x * hi.x + wB.y * hi.y + wB.z * hi.z + wB.w * hi.w;
            acc *= __ldg(ap + v);
            a2sh[u * 26 + v] = make_float2(acc, acc);
        }
    }
    __syncthreads();

    // Pack this thread's two x rows into f32x2 registers (stride 25 ⊥ 32: conflict-free)
    const int t0 = tid, t1 = tid + 64;
    unsigned long long xv[Vv];
    #pragma unroll
    for (int v = 0; v < Vv; v++)
        xv[v] = pack2(xs[t0 * Vv + v], xs[t1 * Vv + v]);
    __syncthreads();   // xs now free for output staging

    #pragma unroll 1
    for (int u = 0; u < Vv; u++) {
        const ulonglong2* arow2 = reinterpret_cast<const ulonglong2*>(a2sh + u * 26);
        unsigned long long acc0 = 0ull, acc1 = 0ull;
        #pragma unroll
        for (int p = 0; p < 12; p++) {
            ulonglong2 w = arow2[p];          // LDS.128, warp-uniform broadcast
            acc0 = fma2(xv[2 * p],     w.x, acc0);
            acc1 = fma2(xv[2 * p + 1], w.y, acc1);
        }
        {   // tail v = 24
            unsigned long long wt =
                *reinterpret_cast<const unsigned long long*>(a2sh + u * 26 + 24);
            acc0 = fma2(xv[24], wt, acc0);
        }
        acc0 = add2(acc0, acc1);
        float lo, hi;
        unpack2(acc0, lo, hi);
        xs[t0 * Vv + u] = lo;
        xs[t1 * Vv + u] = hi;
    }
    __syncthreads();

    float4* op4 = reinterpret_cast<float4*>(out + (size_t)b * (Tt * Vv));
    #pragma unroll
    for (int i = tid; i < (Tt * Vv) / 4; i += 64) __stcs(op4 + i, xs4[i]);
}

extern "C" void kernel_launch(void* const* d_in, const int* in_sizes, int n_in,
                              void* d_out, int out_size) {
    const float* x   = (const float*)d_in[0];
    const float* A   = (const float*)d_in[1];
    const float* w1  = (const float*)d_in[2];
    const float* b1  = (const float*)d_in[3];
    const float* w2  = (const float*)d_in[4];
    const float* b2  = (const float*)d_in[5];
    const float* w4  = (const float*)d_in[6];
    const float* b4  = (const float*)d_in[7];
    const float* sw1 = (const float*)d_in[8];
    const float* sb1 = (const float*)d_in[9];
    const float* sw2 = (const float*)d_in[10];
    const float* sb2 = (const float*)d_in[11];
    float* out = (float*)d_out;

    k1_meanT<<<Nn * Cc, 200>>>(x);
    k2_rel<<<Nn, 512>>>(w1, b1, w2, b2, sw1, sb1, sw2, sb2);
    k3_gemm<<<Nn * Cc, 64>>>(x, A, w4, b4, out);
}

// round 16
// speedup vs baseline: 1.0116x; 1.0116x over previous
#include <cuda_runtime.h>
#include <math.h>

// Problem constants
#define Nn 128
#define Cc 64
#define Tt 128
#define Vv 25
#define Rr 8
#define Hh 12
#define VV2 (Vv * Vv)   // 625

// Scratch (device globals; no allocation allowed)
__device__ float g_xm[Nn * Cc * Vv];            // mean over T   (0.8 MB)
__device__ float g_Aeff[Nn * Cc * VV2];         // effective adjacency (20.5 MB)

// ---------- f32x2 helpers (explicit PTX packed fp32) ----------
__device__ __forceinline__ unsigned long long pack2(float lo, float hi) {
    unsigned long long r;
    asm("mov.b64 %0, {%1, %2};" : "=l"(r) : "f"(lo), "f"(hi));
    return r;
}
__device__ __forceinline__ void unpack2(unsigned long long x, float& lo, float& hi) {
    asm("mov.b64 {%0, %1}, %2;" : "=f"(lo), "=f"(hi) : "l"(x));
}
__device__ __forceinline__ unsigned long long fma2(unsigned long long a,
                                                   unsigned long long b,
                                                   unsigned long long c) {
    unsigned long long d;
    asm("fma.rn.f32x2 %0, %1, %2, %3;" : "=l"(d) : "l"(a), "l"(b), "l"(c));
    return d;
}
__device__ __forceinline__ unsigned long long add2(unsigned long long a,
                                                   unsigned long long b) {
    unsigned long long d;
    asm("add.rn.f32x2 %0, %1, %2;" : "=l"(d) : "l"(a), "l"(b));
    return d;
}

// ================= Kernel 1: xm[n,c,v] = mean_t x[n,c,t,v] =================
// Proven ~19.4us @ ~71% DRAM.
__global__ void __launch_bounds__(200) k1_meanT(const float* __restrict__ x) {
    const int b = blockIdx.x;                 // n*C + c
    const int j = threadIdx.x;                // 0..199
    const float4* xp4 = reinterpret_cast<const float4*>(x + (size_t)b * (Tt * Vv));

    float4 a0 = xp4[j];
    float4 a1 = xp4[j + 200];
    float4 a2 = xp4[j + 400];
    float4 a3 = xp4[j + 600];

    __shared__ float red[800];
    red[4 * j + 0] = a0.x + a1.x + a2.x + a3.x;
    red[4 * j + 1] = a0.y + a1.y + a2.y + a3.y;
    red[4 * j + 2] = a0.z + a1.z + a2.z + a3.z;
    red[4 * j + 3] = a0.w + a1.w + a2.w + a3.w;
    __syncthreads();

    if (j < Vv) {
        float tot = 0.f;
        #pragma unroll
        for (int p = 0; p < 32; p++) tot += red[j + Vv * p];
        g_xm[b * Vv + j] = tot * (1.0f / Tt);
    }
}

// ===== Kernel 2 (merged): SE + relation + Aeff materialization, one block/n =====
// 512 threads. rel kept in smem [r][e]; then all 64 channels of
//   Aeff[n,c,e] = (b4[c] + A[e] + sum_r w4[c,r]*rel[r,e]) * a[v],  e = u*25+v
// are written with coalesced stores (20.5MB total ~= 3.7us DRAM floor).
__global__ void __launch_bounds__(512) k2_adj(
        const float* __restrict__ Astat,
        const float* __restrict__ w1, const float* __restrict__ b1,
        const float* __restrict__ w2, const float* __restrict__ b2,
        const float* __restrict__ w4, const float* __restrict__ b4,
        const float* __restrict__ sw1, const float* __restrict__ sb1,
        const float* __restrict__ sw2, const float* __restrict__ sb2) {
    const int n = blockIdx.x;
    const int tid = threadIdx.x;
    const int NT = 512;

    __shared__ float xm_sh[Cc * Vv];          // 6.4 KB
    __shared__ float rel_sh[Rr * VV2];        // 20 KB  [r][e]
    __shared__ float w1s[Rr * Cc], w2s[Rr * Cc], w4s[Cc * Rr];
    __shared__ float sw1s[Hh * Vv], sw2s[Vv * Hh];
    __shared__ float Aa_s[VV2];               // A[e] (pre-gate)
    __shared__ float av_s[VV2];               // a[v] replicated per e
    __shared__ float b1s[Rr], b2s[Rr], b4s[Cc], sb1s[Hh], sb2s[Vv];
    __shared__ float s_sh[Vv], h_sh[Hh], a_sh[Vv];
    __shared__ float x1_sh[Rr * Vv], x2_sh[Rr * Vv];

    {
        const float4* xm4 = reinterpret_cast<const float4*>(g_xm + n * Cc * Vv);
        float4* sh4 = reinterpret_cast<float4*>(xm_sh);
        if (tid < 400) sh4[tid] = xm4[tid];
    }
    for (int i = tid; i < Rr * Cc; i += NT) { w1s[i] = w1[i]; w2s[i] = w2[i]; w4s[i] = w4[i]; }
    for (int i = tid; i < Hh * Vv; i += NT) { sw1s[i] = sw1[i]; sw2s[i] = sw2[i]; }
    for (int i = tid; i < VV2; i += NT) Aa_s[i] = Astat[i];
    if (tid < Rr) { b1s[tid] = b1[tid]; b2s[tid] = b2[tid]; }
    if (tid < Cc) b4s[tid] = b4[tid];
    if (tid < Hh) sb1s[tid] = sb1[tid];
    if (tid < Vv) sb2s[tid] = sb2[tid];
    __syncthreads();

    // s[v] = mean_c xm; x1/x2 in parallel thread ranges
    if (tid < Vv) {
        float acc = 0.f;
        for (int c = 0; c < Cc; c++) acc += xm_sh[c * Vv + tid];
        s_sh[tid] = acc * (1.0f / Cc);
    }
    if (tid >= 64 && tid < 64 + Rr * Vv) {
        int i = tid - 64;
        int r = i / Vv, v = i % Vv;
        float acc1 = b1s[r], acc2 = b2s[r];
        for (int c = 0; c < Cc; c++) {
            float xm = xm_sh[c * Vv + v];
            acc1 += w1s[r * Cc + c] * xm;
            acc2 += w2s[r * Cc + c] * xm;
        }
        x1_sh[i] = acc1;
        x2_sh[i] = acc2;
    }
    __syncthreads();
    if (tid < Hh) {
        float acc = sb1s[tid];
        for (int v = 0; v < Vv; v++) acc += sw1s[tid * Vv + v] * s_sh[v];
        h_sh[tid] = fmaxf(acc, 0.f);
    }
    __syncthreads();
    if (tid < Vv) {
        float acc = sb2s[tid];
        for (int q = 0; q < Hh; q++) acc += sw2s[tid * Hh + q] * h_sh[q];
        a_sh[tid] = 1.0f / (1.0f + expf(-acc));
    }
    __syncthreads();

    // rel[r][e] = tanh(x1[r,u] - x2[r,v]); also fill av_s[e] = a[v]
    for (int i = tid; i < Rr * VV2; i += NT) {
        int r = i / VV2, e = i - r * VV2;
        int u = e / Vv, v = e - u * Vv;
        rel_sh[i] = tanhf(x1_sh[r * Vv + u] - x2_sh[r * Vv + v]);
    }
    for (int e = tid; e < VV2; e += NT) {
        int v = e % Vv;
        av_s[e] = a_sh[v];
    }
    __syncthreads();

    // Aeff for all 64 channels, coalesced writes
    float* outp = g_Aeff + (size_t)n * Cc * VV2;
    #pragma unroll 1
    for (int c = 0; c < Cc; c++) {
        const float4 wAv = *reinterpret_cast<const float4*>(w4s + c * Rr);
        const float4 wBv = *reinterpret_cast<const float4*>(w4s + c * Rr + 4);
        const float bias = b4s[c];
        float* op = outp + (size_t)c * VV2;
        #pragma unroll 1
        for (int e = tid; e < VV2; e += NT) {
            float acc = bias + Aa_s[e];
            acc += wAv.x * rel_sh[0 * VV2 + e];
            acc += wAv.y * rel_sh[1 * VV2 + e];
            acc += wAv.z * rel_sh[2 * VV2 + e];
            acc += wAv.w * rel_sh[3 * VV2 + e];
            acc += wBv.x * rel_sh[4 * VV2 + e];
            acc += wBv.y * rel_sh[5 * VV2 + e];
            acc += wBv.z * rel_sh[6 * VV2 + e];
            acc += wBv.w * rel_sh[7 * VV2 + e];
            op[e] = acc * av_s[e];
        }
    }
}

// ============ Kernel 3 (R5 body verbatim, measured 63.8us) ============
// One block per (n,c), 64 threads; each thread computes rows t and t+64 as a
// packed f32x2 pair. Aeff duplicated into (a,a) pairs in shared, rows padded
// to 26 pairs (208B, 16B-aligned) -> 12 LDS.128 + 1 LDS.64 + 13 FFMA2 per u.
__global__ void __launch_bounds__(64) k3_gemm(const float* __restrict__ x,
                                              float* __restrict__ out) {
    __shared__ float xs[Tt * Vv];                       // 12.8 KB; reused as out staging
    __shared__ __align__(16) float2 a2sh[Vv * 26];      // padded duplicated pairs

    const int b = blockIdx.x;           // n*C + c
    const int tid = threadIdx.x;        // 0..63

    // Load x tile (float4, coalesced)
    const float4* xp4 = reinterpret_cast<const float4*>(x + (size_t)b * (Tt * Vv));
    float4* xs4 = reinterpret_cast<float4*>(xs);
    #pragma unroll
    for (int i = tid; i < (Tt * Vv) / 4; i += 64) xs4[i] = xp4[i];

    // Load Aeff, duplicate into padded pair rows
    const float* ae = g_Aeff + (size_t)b * VV2;
    for (int i = tid; i < VV2; i += 64) {
        int u = i / Vv, v = i % Vv;
        float w = ae[i];
        a2sh[u * 26 + v] = make_float2(w, w);
    }
    __syncthreads();

    // Pack this thread's two x rows (stride 25 ⊥ 32: conflict-free)
    const int t0 = tid, t1 = tid + 64;
    unsigned long long xv[Vv];
    #pragma unroll
    for (int v = 0; v < Vv; v++)
        xv[v] = pack2(xs[t0 * Vv + v], xs[t1 * Vv + v]);
    __syncthreads();   // xs now free for output staging

    for (int u = 0; u < Vv; u++) {
        const ulonglong2* arow2 = reinterpret_cast<const ulonglong2*>(a2sh + u * 26);
        unsigned long long acc0 = 0ull, acc1 = 0ull;
        #pragma unroll
        for (int p = 0; p < 12; p++) {
            ulonglong2 w = arow2[p];          // LDS.128, warp-uniform broadcast
            acc0 = fma2(xv[2 * p],     w.x, acc0);
            acc1 = fma2(xv[2 * p + 1], w.y, acc1);
        }
        {   // tail v = 24
            unsigned long long wt =
                *reinterpret_cast<const unsigned long long*>(a2sh + u * 26 + 24);
            acc0 = fma2(xv[24], wt, acc0);
        }
        acc0 = add2(acc0, acc1);
        float lo, hi;
        unpack2(acc0, lo, hi);
        xs[t0 * Vv + u] = lo;
        xs[t1 * Vv + u] = hi;
    }
    __syncthreads();

    float4* op4 = reinterpret_cast<float4*>(out + (size_t)b * (Tt * Vv));
    #pragma unroll
    for (int i = tid; i < (Tt * Vv) / 4; i += 64) op4[i] = xs4[i];
}

extern "C" void kernel_launch(void* const* d_in, const int* in_sizes, int n_in,
                              void* d_out, int out_size) {
    const float* x   = (const float*)d_in[0];
    const float* A   = (const float*)d_in[1];
    const float* w1  = (const float*)d_in[2];
    const float* b1  = (const float*)d_in[3];
    const float* w2  = (const float*)d_in[4];
    const float* b2  = (const float*)d_in[5];
    const float* w4  = (const float*)d_in[6];
    const float* b4  = (const float*)d_in[7];
    const float* sw1 = (const float*)d_in[8];
    const float* sb1 = (const float*)d_in[9];
    const float* sw2 = (const float*)d_in[10];
    const float* sb2 = (const float*)d_in[11];
    float* out = (float*)d_out;

    k1_meanT<<<Nn * Cc, 200>>>(x);
    k2_adj<<<Nn, 512>>>(A, w1, b1, w2, b2, w4, b4, sw1, sb1, sw2, sb2);
    k3_gemm<<<Nn * Cc, 64>>>(x, out);
}